// round 3
// baseline (speedup 1.0000x reference)
#include <cuda_runtime.h>

// DWT1DForward (db4, periodic, J=3), fused 3-level kernel.
// out[m] = sum_t h[t] * x[(2m + t - 3) mod N] per level; N halves each level.
// Layout of d_out (floats): [x0: 1024x8192][hi1: 1024x32768][hi2: 1024x16384][hi3: 1024x8192]

#define N0      65536
#define NROWS   1024
#define S       4096
#define CHUNKS  (N0 / S)          // 16
#define THREADS 256

#define XS_LEN  (S + 42)          // x local: covers [-21, S+20]
#define L1_LEN  (S / 2 + 18)      // lo1 local: covers [-9, S/2+8]
#define L2_LEN  (S / 4 + 6)       // lo2 local: covers [-3, S/4+2]

#define OFF_HI1 8388608u          // 1024*8192
#define OFF_HI2 41943040u         // + 1024*32768
#define OFF_HI3 58720256u         // + 1024*16384

// db4 decomposition filters, REVERSED (as the reference passes them in).
#define H0_0 ( 0.23037781330885523f)
#define H0_1 ( 0.7148465705525415f)
#define H0_2 ( 0.6308807679295904f)
#define H0_3 (-0.02798376941698385f)
#define H0_4 (-0.18703481171888114f)
#define H0_5 ( 0.030841381835986965f)
#define H0_6 ( 0.032883011666982945f)
#define H0_7 (-0.010597401784997278f)

#define H1_0 (-0.010597401784997278f)
#define H1_1 (-0.032883011666982945f)
#define H1_2 ( 0.030841381835986965f)
#define H1_3 ( 0.18703481171888114f)
#define H1_4 (-0.02798376941698385f)
#define H1_5 (-0.6308807679295904f)
#define H1_6 ( 0.7148465705525415f)
#define H1_7 (-0.23037781330885523f)

#define CONV_LO(a,b,c,d) \
    fmaf((a).x, H0_0, fmaf((a).y, H0_1, fmaf((b).x, H0_2, fmaf((b).y, H0_3, \
    fmaf((c).x, H0_4, fmaf((c).y, H0_5, fmaf((d).x, H0_6, (d).y * H0_7)))))))

#define CONV_HI(a,b,c,d) \
    fmaf((a).x, H1_0, fmaf((a).y, H1_1, fmaf((b).x, H1_2, fmaf((b).y, H1_3, \
    fmaf((c).x, H1_4, fmaf((c).y, H1_5, fmaf((d).x, H1_6, (d).y * H1_7)))))))

__global__ __launch_bounds__(THREADS)
void dwt3_fused_kernel(const float* __restrict__ x, float* __restrict__ out)
{
    __shared__ __align__(16) float xs[XS_LEN + 2];
    __shared__ __align__(16) float lo1[L1_LEN + 2];
    __shared__ __align__(16) float lo2[L2_LEN + 2];

    const int cta   = blockIdx.x;
    const int row   = cta >> 4;            // / CHUNKS
    const int chunk = cta & (CHUNKS - 1);
    const int base  = chunk * S;
    const int tid   = threadIdx.x;

    const float* __restrict__ xrow = x + (size_t)row * N0;

    // ---- Stage 0: load input chunk with periodic halo [-21, S+20] ----
    // Interior [base, base+S) via LDG.128: base is a multiple of 4096 floats,
    // so xrow+base is 16B-aligned.
    {
        const float4* __restrict__ xb = reinterpret_cast<const float4*>(xrow + base);
        #pragma unroll
        for (int k = tid; k < S / 4; k += THREADS) {
            float4 v = xb[k];
            int i = 21 + 4 * k;
            xs[i]     = v.x;
            xs[i + 1] = v.y;
            xs[i + 2] = v.z;
            xs[i + 3] = v.w;
        }
        // 21-element halos on each side, periodic wrap.
        if (tid < 42) {
            int i = (tid < 21) ? tid : (S + tid);   // 0..20 and S+21..S+41
            int g = (base - 21 + i + N0) & (N0 - 1);
            xs[i] = xrow[g];
        }
    }
    __syncthreads();

    // ---- Level 1 ----
    // lo1 local w in [0, L1_LEN): output index j1 = w - 9; window = xs[2w .. 2w+7]
    {
        float* __restrict__ hi1_out =
            out + OFF_HI1 + (size_t)row * (N0 / 2) + (size_t)chunk * (S / 2);
        const float2* __restrict__ xs2 = reinterpret_cast<const float2*>(xs);
        for (int w = tid; w < L1_LEN; w += THREADS) {
            float2 a = xs2[w];
            float2 b = xs2[w + 1];
            float2 c = xs2[w + 2];
            float2 d = xs2[w + 3];
            lo1[w] = CONV_LO(a, b, c, d);
            int j = w - 9;
            if ((unsigned)j < (unsigned)(S / 2)) {
                hi1_out[j] = CONV_HI(a, b, c, d);
            }
        }
    }
    __syncthreads();

    // ---- Level 2 ----
    // lo2 local w in [0, L2_LEN): output index j2 = w - 3; window = lo1[2w .. 2w+7]
    {
        float* __restrict__ hi2_out =
            out + OFF_HI2 + (size_t)row * (N0 / 4) + (size_t)chunk * (S / 4);
        const float2* __restrict__ l1v = reinterpret_cast<const float2*>(lo1);
        for (int w = tid; w < L2_LEN; w += THREADS) {
            float2 a = l1v[w];
            float2 b = l1v[w + 1];
            float2 c = l1v[w + 2];
            float2 d = l1v[w + 3];
            lo2[w] = CONV_LO(a, b, c, d);
            int j = w - 3;
            if ((unsigned)j < (unsigned)(S / 4)) {
                hi2_out[j] = CONV_HI(a, b, c, d);
            }
        }
    }
    __syncthreads();

    // ---- Level 3 ----
    // output j3 in [0, S/8): window = lo2[2*j3 .. 2*j3+7]
    {
        float* __restrict__ x0_out =
            out + (size_t)row * (N0 / 8) + (size_t)chunk * (S / 8);
        float* __restrict__ hi3_out =
            out + OFF_HI3 + (size_t)row * (N0 / 8) + (size_t)chunk * (S / 8);
        const float2* __restrict__ l2v = reinterpret_cast<const float2*>(lo2);
        for (int w = tid; w < S / 8; w += THREADS) {
            float2 a = l2v[w];
            float2 b = l2v[w + 1];
            float2 c = l2v[w + 2];
            float2 d = l2v[w + 3];
            x0_out[w]  = CONV_LO(a, b, c, d);
            hi3_out[w] = CONV_HI(a, b, c, d);
        }
    }
}

extern "C" void kernel_launch(void* const* d_in, const int* in_sizes, int n_in,
                              void* d_out, int out_size)
{
    const float* x = (const float*)d_in[0];
    float* out = (float*)d_out;
    dwt3_fused_kernel<<<NROWS * CHUNKS, THREADS>>>(x, out);
}

// round 6
// speedup vs baseline: 1.2170x; 1.2170x over previous
#include <cuda_runtime.h>

// DWT1DForward (db4, periodic, J=3), fused 3-level kernel, polyphase smem layout.
// out[m] = sum_t h[t] * x[(2m + t - 3) mod N] per level; N halves each level.
// d_out floats: [x0: 1024x8192][hi1: 1024x32768][hi2: 1024x16384][hi3: 1024x8192]

#define N0      65536
#define NROWS   1024
#define S       4096
#define CHUNKS  (N0 / S)          // 16
#define THREADS 256

#define OFF_HI1 8388608u          // 1024*8192
#define OFF_HI2 41943040u         // + 1024*32768
#define OFF_HI3 58720256u         // + 1024*16384

#define L1_GROUPS 518             // m0 = 4p-12, covers lo1[-12..2059]
#define L2_GROUPS 258             // n0 = 4q-4,  covers lo2[-4..1027]
#define L3_GROUPS 128             // j0 = 4s,    outputs [0,512)

// db4 decomposition filters, REVERSED (as the reference passes them in).
#define H0_0 ( 0.23037781330885523f)
#define H0_1 ( 0.7148465705525415f)
#define H0_2 ( 0.6308807679295904f)
#define H0_3 (-0.02798376941698385f)
#define H0_4 (-0.18703481171888114f)
#define H0_5 ( 0.030841381835986965f)
#define H0_6 ( 0.032883011666982945f)
#define H0_7 (-0.010597401784997278f)

#define H1_0 (-0.010597401784997278f)
#define H1_1 (-0.032883011666982945f)
#define H1_2 ( 0.030841381835986965f)
#define H1_3 ( 0.18703481171888114f)
#define H1_4 (-0.02798376941698385f)
#define H1_5 (-0.6308807679295904f)
#define H1_6 ( 0.7148465705525415f)
#define H1_7 (-0.23037781330885523f)

// o0..o3 are the odd-sample taps (x[2m-3],x[2m-1],x[2m+1],x[2m+3]),
// e0..e3 the even-sample taps (x[2m-2],x[2m],x[2m+2],x[2m+4]).
#define CONV_LO(o0,o1,o2,o3,e0,e1,e2,e3) \
    fmaf(o0, H0_0, fmaf(o1, H0_2, fmaf(o2, H0_4, fmaf(o3, H0_6, \
    fmaf(e0, H0_1, fmaf(e1, H0_3, fmaf(e2, H0_5, (e3) * H0_7)))))))

#define CONV_HI(o0,o1,o2,o3,e0,e1,e2,e3) \
    fmaf(o0, H1_0, fmaf(o1, H1_2, fmaf(o2, H1_4, fmaf(o3, H1_6, \
    fmaf(e0, H1_1, fmaf(e1, H1_3, fmaf(e2, H1_5, (e3) * H1_7)))))))

__global__ __launch_bounds__(THREADS)
void dwt3_poly_kernel(const float* __restrict__ x, float* __restrict__ out)
{
    // Polyphase shared arrays (all float4-read-aligned).
    __shared__ __align__(16) float XE1[2080];      // XE1[j] = x_loc[2j-26]
    __shared__ __align__(16) float XO1[2080];      // XO1[j] = x_loc[2j-27]
    __shared__ __align__(16) float XE2buf[1044];   // XE2 = buf+4; XE2[j] = lo1_e[j-5]
    __shared__ __align__(16) float XO2[1040];      // XO2[j] = lo1_o[j-6]
    __shared__ __align__(16) float XE3buf[528];    // XE3 = buf+4; XE3[j] = lo2_e[j-1]
    __shared__ __align__(16) float XO3[528];       // XO3[j] = lo2_o[j-2]

    float* const XE2 = XE2buf + 4;
    float* const XE3 = XE3buf + 4;

    const int cta   = blockIdx.x;
    const int row   = cta >> 4;            // / CHUNKS
    const int chunk = cta & (CHUNKS - 1);
    const int base  = chunk * S;
    const int tid   = threadIdx.x;

    const float* __restrict__ xrow = x + (size_t)row * N0;

    // ---- Stage 0: load chunk (+halo x[-27..S+28]) de-interleaved into XE1/XO1 ----
    {
        const float4* __restrict__ xb = reinterpret_cast<const float4*>(xrow + base);
        #pragma unroll
        for (int k = tid; k < S / 4; k += THREADS) {
            float4 v = xb[k];
            XE1[2 * k + 13] = v.x;                 // x[4k]   even
            XE1[2 * k + 14] = v.z;                 // x[4k+2] even
            *reinterpret_cast<float2*>(&XO1[2 * k + 14]) = make_float2(v.y, v.w);
        }
        if (tid < 56) {                            // halo: q in [-27,-1] U [S, S+28]
            int q = (tid < 27) ? (tid - 27) : (S + tid - 27);
            float v = xrow[(base + q + N0) & (N0 - 1)];
            if (q & 1) XO1[(q + 27) >> 1] = v;     // odd sample
            else       XE1[(q + 26) >> 1] = v;     // even sample
        }
    }
    __syncthreads();

    // ---- Level 1: groups of 4 outputs, m0 = 4p - 12 ----
    {
        float* __restrict__ hi1_out =
            out + OFF_HI1 + (size_t)row * (N0 / 2) + (size_t)chunk * (S / 2);
        const float4* __restrict__ Ov = reinterpret_cast<const float4*>(XO1);
        const float4* __restrict__ Ev = reinterpret_cast<const float4*>(XE1);
        for (int p = tid; p < L1_GROUPS; p += THREADS) {
            float4 oA = Ov[p], oB = Ov[p + 1];
            float4 eA = Ev[p], eB = Ev[p + 1];
            float lo0 = CONV_LO(oA.x, oA.y, oA.z, oA.w, eA.x, eA.y, eA.z, eA.w);
            float lo1 = CONV_LO(oA.y, oA.z, oA.w, oB.x, eA.y, eA.z, eA.w, eB.x);
            float lo2 = CONV_LO(oA.z, oA.w, oB.x, oB.y, eA.z, eA.w, eB.x, eB.y);
            float lo3 = CONV_LO(oA.w, oB.x, oB.y, oB.z, eA.w, eB.x, eB.y, eB.z);
            // scatter lo into level-2 polyphase arrays
            XE2[2 * p - 1] = lo0;
            XE2[2 * p]     = lo2;
            *reinterpret_cast<float2*>(&XO2[2 * p]) = make_float2(lo1, lo3);
            if (p >= 3 && p <= 514) {              // interior: outputs 0..2047
                float4 hv;
                hv.x = CONV_HI(oA.x, oA.y, oA.z, oA.w, eA.x, eA.y, eA.z, eA.w);
                hv.y = CONV_HI(oA.y, oA.z, oA.w, oB.x, eA.y, eA.z, eA.w, eB.x);
                hv.z = CONV_HI(oA.z, oA.w, oB.x, oB.y, eA.z, eA.w, eB.x, eB.y);
                hv.w = CONV_HI(oA.w, oB.x, oB.y, oB.z, eA.w, eB.x, eB.y, eB.z);
                *reinterpret_cast<float4*>(hi1_out + 4 * p - 12) = hv;
            }
        }
    }
    __syncthreads();

    // ---- Level 2: n0 = 4q - 4 ----
    {
        float* __restrict__ hi2_out =
            out + OFF_HI2 + (size_t)row * (N0 / 4) + (size_t)chunk * (S / 4);
        const float4* __restrict__ Ov = reinterpret_cast<const float4*>(XO2);
        const float4* __restrict__ Ev = reinterpret_cast<const float4*>(XE2);
        for (int q = tid; q < L2_GROUPS; q += THREADS) {
            float4 oA = Ov[q], oB = Ov[q + 1];
            float4 eA = Ev[q], eB = Ev[q + 1];
            float lo0 = CONV_LO(oA.x, oA.y, oA.z, oA.w, eA.x, eA.y, eA.z, eA.w);
            float lo1 = CONV_LO(oA.y, oA.z, oA.w, oB.x, eA.y, eA.z, eA.w, eB.x);
            float lo2 = CONV_LO(oA.z, oA.w, oB.x, oB.y, eA.z, eA.w, eB.x, eB.y);
            float lo3 = CONV_LO(oA.w, oB.x, oB.y, oB.z, eA.w, eB.x, eB.y, eB.z);
            XE3[2 * q - 1] = lo0;
            XE3[2 * q]     = lo2;
            *reinterpret_cast<float2*>(&XO3[2 * q]) = make_float2(lo1, lo3);
            if (q >= 1 && q <= 256) {              // interior: outputs 0..1023
                float4 hv;
                hv.x = CONV_HI(oA.x, oA.y, oA.z, oA.w, eA.x, eA.y, eA.z, eA.w);
                hv.y = CONV_HI(oA.y, oA.z, oA.w, oB.x, eA.y, eA.z, eA.w, eB.x);
                hv.z = CONV_HI(oA.z, oA.w, oB.x, oB.y, eA.z, eA.w, eB.x, eB.y);
                hv.w = CONV_HI(oA.w, oB.x, oB.y, oB.z, eA.w, eB.x, eB.y, eB.z);
                *reinterpret_cast<float4*>(hi2_out + 4 * q - 4) = hv;
            }
        }
    }
    __syncthreads();

    // ---- Level 3: j0 = 4s ----
    {
        float* __restrict__ x0_out =
            out + (size_t)row * (N0 / 8) + (size_t)chunk * (S / 8);
        float* __restrict__ hi3_out =
            out + OFF_HI3 + (size_t)row * (N0 / 8) + (size_t)chunk * (S / 8);
        const float4* __restrict__ Ov = reinterpret_cast<const float4*>(XO3);
        const float4* __restrict__ Ev = reinterpret_cast<const float4*>(XE3);
        for (int s = tid; s < L3_GROUPS; s += THREADS) {
            float4 oA = Ov[s], oB = Ov[s + 1];
            float4 eA = Ev[s], eB = Ev[s + 1];
            float4 lv, hv;
            lv.x = CONV_LO(oA.x, oA.y, oA.z, oA.w, eA.x, eA.y, eA.z, eA.w);
            lv.y = CONV_LO(oA.y, oA.z, oA.w, oB.x, eA.y, eA.z, eA.w, eB.x);
            lv.z = CONV_LO(oA.z, oA.w, oB.x, oB.y, eA.z, eA.w, eB.x, eB.y);
            lv.w = CONV_LO(oA.w, oB.x, oB.y, oB.z, eA.w, eB.x, eB.y, eB.z);
            hv.x = CONV_HI(oA.x, oA.y, oA.z, oA.w, eA.x, eA.y, eA.z, eA.w);
            hv.y = CONV_HI(oA.y, oA.z, oA.w, oB.x, eA.y, eA.z, eA.w, eB.x);
            hv.z = CONV_HI(oA.z, oA.w, oB.x, oB.y, eA.z, eA.w, eB.x, eB.y);
            hv.w = CONV_HI(oA.w, oB.x, oB.y, oB.z, eA.w, eB.x, eB.y, eB.z);
            *reinterpret_cast<float4*>(x0_out + 4 * s)  = lv;
            *reinterpret_cast<float4*>(hi3_out + 4 * s) = hv;
        }
    }
}

extern "C" void kernel_launch(void* const* d_in, const int* in_sizes, int n_in,
                              void* d_out, int out_size)
{
    const float* x = (const float*)d_in[0];
    float* out = (float*)d_out;
    dwt3_poly_kernel<<<NROWS * CHUNKS, THREADS>>>(x, out);
}

// round 7
// speedup vs baseline: 1.2281x; 1.0091x over previous
#include <cuda_runtime.h>

// DWT1DForward (db4, periodic, J=3), fused 3-level kernel, polyphase smem layout.
// S=2048 chunks / 128-thread CTAs for ~15 concurrent CTAs/SM (phase overlap).
// out[m] = sum_t h[t] * x[(2m + t - 3) mod N] per level; N halves each level.
// d_out floats: [x0: 1024x8192][hi1: 1024x32768][hi2: 1024x16384][hi3: 1024x8192]

#define N0      65536
#define NROWS   1024
#define S       2048
#define CHUNKS  (N0 / S)          // 32
#define THREADS 128

#define OFF_HI1 8388608u          // 1024*8192
#define OFF_HI2 41943040u         // + 1024*32768
#define OFF_HI3 58720256u         // + 1024*16384

#define L1_GROUPS 262             // m0 = 4p-12, covers lo1[-12..1035]
#define L2_GROUPS 130             // n0 = 4q-4,  covers lo2[-4..515]
#define L3_GROUPS 64              // j0 = 4s,    outputs [0,256)

// db4 decomposition filters, REVERSED (as the reference passes them in).
#define H0_0 ( 0.23037781330885523f)
#define H0_1 ( 0.7148465705525415f)
#define H0_2 ( 0.6308807679295904f)
#define H0_3 (-0.02798376941698385f)
#define H0_4 (-0.18703481171888114f)
#define H0_5 ( 0.030841381835986965f)
#define H0_6 ( 0.032883011666982945f)
#define H0_7 (-0.010597401784997278f)

#define H1_0 (-0.010597401784997278f)
#define H1_1 (-0.032883011666982945f)
#define H1_2 ( 0.030841381835986965f)
#define H1_3 ( 0.18703481171888114f)
#define H1_4 (-0.02798376941698385f)
#define H1_5 (-0.6308807679295904f)
#define H1_6 ( 0.7148465705525415f)
#define H1_7 (-0.23037781330885523f)

// o0..o3 odd-sample taps (x[2m-3],x[2m-1],x[2m+1],x[2m+3]),
// e0..e3 even-sample taps (x[2m-2],x[2m],x[2m+2],x[2m+4]).
#define CONV_LO(o0,o1,o2,o3,e0,e1,e2,e3) \
    fmaf(o0, H0_0, fmaf(o1, H0_2, fmaf(o2, H0_4, fmaf(o3, H0_6, \
    fmaf(e0, H0_1, fmaf(e1, H0_3, fmaf(e2, H0_5, (e3) * H0_7)))))))

#define CONV_HI(o0,o1,o2,o3,e0,e1,e2,e3) \
    fmaf(o0, H1_0, fmaf(o1, H1_2, fmaf(o2, H1_4, fmaf(o3, H1_6, \
    fmaf(e0, H1_1, fmaf(e1, H1_3, fmaf(e2, H1_5, (e3) * H1_7)))))))

__global__ __launch_bounds__(THREADS)
void dwt3_poly128_kernel(const float* __restrict__ x, float* __restrict__ out)
{
    // Polyphase shared arrays (all float4-read-aligned).
    __shared__ __align__(16) float XE1[1056];      // XE1[j] = x_loc[2j-26]
    __shared__ __align__(16) float XO1[1056];      // XO1[j] = x_loc[2j-27]
    __shared__ __align__(16) float XE2buf[528];    // XE2 = buf+4; XE2[j] = lo1[2j-10]
    __shared__ __align__(16) float XO2[528];       // XO2[j] = lo1[2j-11]
    __shared__ __align__(16) float XE3buf[272];    // XE3 = buf+4; XE3[j] = lo2[2j-2]
    __shared__ __align__(16) float XO3[272];       // XO3[j] = lo2[2j-3]

    float* const XE2 = XE2buf + 4;
    float* const XE3 = XE3buf + 4;

    const int cta   = blockIdx.x;
    const int row   = cta >> 5;            // / CHUNKS
    const int chunk = cta & (CHUNKS - 1);
    const int base  = chunk * S;
    const int tid   = threadIdx.x;

    const float* __restrict__ xrow = x + (size_t)row * N0;

    // ---- Stage 0: load chunk (+halo x[-27..S+26]) de-interleaved into XE1/XO1 ----
    {
        // Halo first so its (possibly far) loads issue early.
        if (tid < 54) {                            // q in [-27,-1] U [S, S+26]
            int q = (tid < 27) ? (tid - 27) : (S + tid - 27);
            float v = xrow[(base + q + N0) & (N0 - 1)];
            if (q & 1) XO1[(q + 27) >> 1] = v;     // odd sample
            else       XE1[(q + 26) >> 1] = v;     // even sample
        }
        const float4* __restrict__ xb = reinterpret_cast<const float4*>(xrow + base);
        #pragma unroll
        for (int it = 0; it < S / 4 / THREADS; it++) {
            int k = tid + it * THREADS;
            float4 v = xb[k];
            XE1[2 * k + 13] = v.x;                 // x[4k]   even
            XE1[2 * k + 14] = v.z;                 // x[4k+2] even
            *reinterpret_cast<float2*>(&XO1[2 * k + 14]) = make_float2(v.y, v.w);
        }
    }
    __syncthreads();

    // ---- Level 1: groups of 4 outputs, m0 = 4p - 12 ----
    {
        float* __restrict__ hi1_out =
            out + OFF_HI1 + (size_t)row * (N0 / 2) + (size_t)chunk * (S / 2);
        const float4* __restrict__ Ov = reinterpret_cast<const float4*>(XO1);
        const float4* __restrict__ Ev = reinterpret_cast<const float4*>(XE1);
        for (int p = tid; p < L1_GROUPS; p += THREADS) {
            float4 oA = Ov[p], oB = Ov[p + 1];
            float4 eA = Ev[p], eB = Ev[p + 1];
            float lo0 = CONV_LO(oA.x, oA.y, oA.z, oA.w, eA.x, eA.y, eA.z, eA.w);
            float lo1 = CONV_LO(oA.y, oA.z, oA.w, oB.x, eA.y, eA.z, eA.w, eB.x);
            float lo2 = CONV_LO(oA.z, oA.w, oB.x, oB.y, eA.z, eA.w, eB.x, eB.y);
            float lo3 = CONV_LO(oA.w, oB.x, oB.y, oB.z, eA.w, eB.x, eB.y, eB.z);
            // scatter lo into level-2 polyphase arrays
            XE2[2 * p - 1] = lo0;
            XE2[2 * p]     = lo2;
            *reinterpret_cast<float2*>(&XO2[2 * p]) = make_float2(lo1, lo3);
            if (p >= 3 && p <= 258) {              // interior: outputs 0..1023
                float4 hv;
                hv.x = CONV_HI(oA.x, oA.y, oA.z, oA.w, eA.x, eA.y, eA.z, eA.w);
                hv.y = CONV_HI(oA.y, oA.z, oA.w, oB.x, eA.y, eA.z, eA.w, eB.x);
                hv.z = CONV_HI(oA.z, oA.w, oB.x, oB.y, eA.z, eA.w, eB.x, eB.y);
                hv.w = CONV_HI(oA.w, oB.x, oB.y, oB.z, eA.w, eB.x, eB.y, eB.z);
                *reinterpret_cast<float4*>(hi1_out + 4 * p - 12) = hv;
            }
        }
    }
    __syncthreads();

    // ---- Level 2: n0 = 4q - 4 ----
    {
        float* __restrict__ hi2_out =
            out + OFF_HI2 + (size_t)row * (N0 / 4) + (size_t)chunk * (S / 4);
        const float4* __restrict__ Ov = reinterpret_cast<const float4*>(XO2);
        const float4* __restrict__ Ev = reinterpret_cast<const float4*>(XE2);
        for (int q = tid; q < L2_GROUPS; q += THREADS) {
            float4 oA = Ov[q], oB = Ov[q + 1];
            float4 eA = Ev[q], eB = Ev[q + 1];
            float lo0 = CONV_LO(oA.x, oA.y, oA.z, oA.w, eA.x, eA.y, eA.z, eA.w);
            float lo1 = CONV_LO(oA.y, oA.z, oA.w, oB.x, eA.y, eA.z, eA.w, eB.x);
            float lo2 = CONV_LO(oA.z, oA.w, oB.x, oB.y, eA.z, eA.w, eB.x, eB.y);
            float lo3 = CONV_LO(oA.w, oB.x, oB.y, oB.z, eA.w, eB.x, eB.y, eB.z);
            XE3[2 * q - 1] = lo0;
            XE3[2 * q]     = lo2;
            *reinterpret_cast<float2*>(&XO3[2 * q]) = make_float2(lo1, lo3);
            if (q >= 1 && q <= 128) {              // interior: outputs 0..511
                float4 hv;
                hv.x = CONV_HI(oA.x, oA.y, oA.z, oA.w, eA.x, eA.y, eA.z, eA.w);
                hv.y = CONV_HI(oA.y, oA.z, oA.w, oB.x, eA.y, eA.z, eA.w, eB.x);
                hv.z = CONV_HI(oA.z, oA.w, oB.x, oB.y, eA.z, eA.w, eB.x, eB.y);
                hv.w = CONV_HI(oA.w, oB.x, oB.y, oB.z, eA.w, eB.x, eB.y, eB.z);
                *reinterpret_cast<float4*>(hi2_out + 4 * q - 4) = hv;
            }
        }
    }
    __syncthreads();

    // ---- Level 3: j0 = 4s ----
    {
        float* __restrict__ x0_out =
            out + (size_t)row * (N0 / 8) + (size_t)chunk * (S / 8);
        float* __restrict__ hi3_out =
            out + OFF_HI3 + (size_t)row * (N0 / 8) + (size_t)chunk * (S / 8);
        const float4* __restrict__ Ov = reinterpret_cast<const float4*>(XO3);
        const float4* __restrict__ Ev = reinterpret_cast<const float4*>(XE3);
        #pragma unroll
        for (int it = 0; it < 1; it++) {
            int s = tid + it * THREADS;
            if (s < L3_GROUPS) {
                float4 oA = Ov[s], oB = Ov[s + 1];
                float4 eA = Ev[s], eB = Ev[s + 1];
                float4 lv, hv;
                lv.x = CONV_LO(oA.x, oA.y, oA.z, oA.w, eA.x, eA.y, eA.z, eA.w);
                lv.y = CONV_LO(oA.y, oA.z, oA.w, oB.x, eA.y, eA.z, eA.w, eB.x);
                lv.z = CONV_LO(oA.z, oA.w, oB.x, oB.y, eA.z, eA.w, eB.x, eB.y);
                lv.w = CONV_LO(oA.w, oB.x, oB.y, oB.z, eA.w, eB.x, eB.y, eB.z);
                hv.x = CONV_HI(oA.x, oA.y, oA.z, oA.w, eA.x, eA.y, eA.z, eA.w);
                hv.y = CONV_HI(oA.y, oA.z, oA.w, oB.x, eA.y, eA.z, eA.w, eB.x);
                hv.z = CONV_HI(oA.z, oA.w, oB.x, oB.y, eA.z, eA.w, eB.x, eB.y);
                hv.w = CONV_HI(oA.w, oB.x, oB.y, oB.z, eA.w, eB.x, eB.y, eB.z);
                *reinterpret_cast<float4*>(x0_out + 4 * s)  = lv;
                *reinterpret_cast<float4*>(hi3_out + 4 * s) = hv;
            }
        }
    }
}

extern "C" void kernel_launch(void* const* d_in, const int* in_sizes, int n_in,
                              void* d_out, int out_size)
{
    const float* x = (const float*)d_in[0];
    float* out = (float*)d_out;
    dwt3_poly128_kernel<<<NROWS * CHUNKS, THREADS>>>(x, out);
}

// round 8
// speedup vs baseline: 1.3154x; 1.0711x over previous
#include <cuda_runtime.h>

// DWT1DForward (db4, periodic, J=3) — fully register-resident cascade.
// Thread t owns x[16t..16t+15]; computes lo1/hi1[8t..8t+7], lo2/hi2[4t..4t+3],
// lo3/hi3[2t..2t+1] in registers. Halos: shfl (level 1) + smem edge slots (2,3).
// d_out floats: [x0: 1024x8192][hi1: 1024x32768][hi2: 1024x16384][hi3: 1024x8192]

#define N0      65536
#define NROWS   1024
#define S       2048
#define CHUNKS  (N0 / S)          // 32
#define THREADS 128

#define OFF_HI1 8388608u
#define OFF_HI2 41943040u
#define OFF_HI3 58720256u

// db4 decomposition filters, REVERSED (as the reference passes them in).
#define H0_0 ( 0.23037781330885523f)
#define H0_1 ( 0.7148465705525415f)
#define H0_2 ( 0.6308807679295904f)
#define H0_3 (-0.02798376941698385f)
#define H0_4 (-0.18703481171888114f)
#define H0_5 ( 0.030841381835986965f)
#define H0_6 ( 0.032883011666982945f)
#define H0_7 (-0.010597401784997278f)

#define H1_0 (-0.010597401784997278f)
#define H1_1 (-0.032883011666982945f)
#define H1_2 ( 0.030841381835986965f)
#define H1_3 ( 0.18703481171888114f)
#define H1_4 (-0.02798376941698385f)
#define H1_5 (-0.6308807679295904f)
#define H1_6 ( 0.7148465705525415f)
#define H1_7 (-0.23037781330885523f)

// out[m] = sum_{i=0..7} H_i * x[2m-3+i]
__device__ __forceinline__ float conv_lo(const float* p) {
    return fmaf(p[0], H0_0, fmaf(p[1], H0_1, fmaf(p[2], H0_2, fmaf(p[3], H0_3,
           fmaf(p[4], H0_4, fmaf(p[5], H0_5, fmaf(p[6], H0_6, p[7] * H0_7)))))));
}
__device__ __forceinline__ float conv_hi(const float* p) {
    return fmaf(p[0], H1_0, fmaf(p[1], H1_1, fmaf(p[2], H1_2, fmaf(p[3], H1_3,
           fmaf(p[4], H1_4, fmaf(p[5], H1_5, fmaf(p[6], H1_6, p[7] * H1_7)))))));
}

__global__ __launch_bounds__(THREADS)
void dwt3_reg_kernel(const float* __restrict__ x, float* __restrict__ out)
{
    // Edge-slot arrays: slot u (u in [-1,128]) stored at index u+1.
    // eh*[u+1] = last-3 of thread u's lo values; el*[u+1] = first-3.
    __shared__ __align__(16) float4 eh1[THREADS + 2];
    __shared__ __align__(16) float4 el1[THREADS + 2];
    __shared__ __align__(16) float4 eh2[THREADS + 2];
    __shared__ __align__(16) float4 el2[THREADS + 2];

    const int cta   = blockIdx.x;
    const int row   = cta >> 5;              // / CHUNKS
    const int chunk = cta & (CHUNKS - 1);
    const int base  = chunk * S;
    const int t     = threadIdx.x;

    const float* __restrict__ xrow = x + (size_t)row * N0;

    // ---- Load owned span x_loc[16t .. 16t+15]; xv[i] = x_loc[16t-3+i] ----
    float xv[22];
    {
        const float4* __restrict__ xb =
            reinterpret_cast<const float4*>(xrow + base + 16 * t);
        float4 q0 = xb[0], q1 = xb[1], q2 = xb[2], q3 = xb[3];
        xv[3]  = q0.x; xv[4]  = q0.y; xv[5]  = q0.z; xv[6]  = q0.w;
        xv[7]  = q1.x; xv[8]  = q1.y; xv[9]  = q1.z; xv[10] = q1.w;
        xv[11] = q2.x; xv[12] = q2.y; xv[13] = q2.z; xv[14] = q2.w;
        xv[15] = q3.x; xv[16] = q3.y; xv[17] = q3.z; xv[18] = q3.w;
    }
    // Halo via shfl from neighbor lanes; warp-edge lanes load wrapped from gmem.
    {
        float a = __shfl_up_sync(0xffffffffu, xv[16], 1);
        float b = __shfl_up_sync(0xffffffffu, xv[17], 1);
        float c = __shfl_up_sync(0xffffffffu, xv[18], 1);
        if ((t & 31) == 0) {
            int g = base + 16 * t - 3;
            a = xrow[(g + N0)     & (N0 - 1)];
            b = xrow[(g + 1 + N0) & (N0 - 1)];
            c = xrow[(g + 2 + N0) & (N0 - 1)];
        }
        xv[0] = a; xv[1] = b; xv[2] = c;
        a = __shfl_down_sync(0xffffffffu, xv[3], 1);
        b = __shfl_down_sync(0xffffffffu, xv[4], 1);
        c = __shfl_down_sync(0xffffffffu, xv[5], 1);
        if ((t & 31) == 31) {
            int g = base + 16 * t + 16;
            a = xrow[g & (N0 - 1)];
            b = xrow[(g + 1) & (N0 - 1)];
            c = xrow[(g + 2) & (N0 - 1)];
        }
        xv[19] = a; xv[20] = b; xv[21] = c;
    }

    // ---- Level 1: lo1[8t+k], hi1[8t+k], k=0..7; window xv[2k..2k+7] ----
    float lo1[8];
    {
        #pragma unroll
        for (int k = 0; k < 8; k++) lo1[k] = conv_lo(xv + 2 * k);

        float* __restrict__ hi1_out =
            out + OFF_HI1 + (size_t)row * (N0 / 2) + (size_t)chunk * (S / 2) + 8 * t;
        float4 h0 = make_float4(conv_hi(xv + 0), conv_hi(xv + 2),
                                conv_hi(xv + 4), conv_hi(xv + 6));
        float4 h1 = make_float4(conv_hi(xv + 8), conv_hi(xv + 10),
                                conv_hi(xv + 12), conv_hi(xv + 14));
        *reinterpret_cast<float4*>(hi1_out)     = h0;
        *reinterpret_cast<float4*>(hi1_out + 4) = h1;

        eh1[t + 1] = make_float4(lo1[5], lo1[6], lo1[7], 0.0f);
        el1[t + 1] = make_float4(lo1[0], lo1[1], lo1[2], 0.0f);
    }

    // ---- Chunk-edge halo slots (threads 0 and 127), before sync ----
    if (t == 0) {
        float hx[24];                         // hx[i] = x_loc[-21+i]
        #pragma unroll
        for (int i = 0; i < 21; i++)
            hx[i] = xrow[(base - 21 + i + N0) & (N0 - 1)];
        hx[21] = xv[3]; hx[22] = xv[4]; hx[23] = xv[5];   // x[0..2]
        float l1h[12];                        // l1h[i] = lo1[-9+i]
        #pragma unroll
        for (int u = 0; u < 9; u++) l1h[u] = conv_lo(hx + 2 * u);
        l1h[9] = lo1[0]; l1h[10] = lo1[1]; l1h[11] = lo1[2];
        eh1[0] = make_float4(l1h[6], l1h[7], l1h[8], 0.0f);   // lo1[-3..-1]
        eh2[0] = make_float4(conv_lo(l1h + 0), conv_lo(l1h + 2),
                             conv_lo(l1h + 4), 0.0f);         // lo2[-3..-1]
    }
    if (t == THREADS - 1) {
        float hx[24];                         // hx[i] = x_loc[2045+i]
        hx[0] = xv[16]; hx[1] = xv[17]; hx[2] = xv[18];       // x[2045..2047]
        #pragma unroll
        for (int i = 3; i < 24; i++)
            hx[i] = xrow[(base + 2045 + i) & (N0 - 1)];       // x[2048..2068]
        float l1h[12];                        // l1h[i] = lo1[1021+i]
        l1h[0] = lo1[5]; l1h[1] = lo1[6]; l1h[2] = lo1[7];
        #pragma unroll
        for (int u = 0; u < 9; u++) l1h[3 + u] = conv_lo(hx + 2 * u);  // lo1[1024+u]
        el1[THREADS + 1] = make_float4(l1h[3], l1h[4], l1h[5], 0.0f);  // lo1[1024..1026]
        el2[THREADS + 1] = make_float4(conv_lo(l1h + 0), conv_lo(l1h + 2),
                                       conv_lo(l1h + 4), 0.0f);        // lo2[512..514]
    }
    __syncthreads();

    // ---- Level 2: lv[i] = lo1[8t-3+i]; outputs 4t..4t+3 ----
    float lo2r[4];
    {
        float4 hl = eh1[t];                   // lo1[8t-3..8t-1]
        float4 lr = el1[t + 2];               // lo1[8t+8..8t+10]
        float lv[14];
        lv[0] = hl.x; lv[1] = hl.y; lv[2] = hl.z;
        #pragma unroll
        for (int k = 0; k < 8; k++) lv[3 + k] = lo1[k];
        lv[11] = lr.x; lv[12] = lr.y; lv[13] = lr.z;

        #pragma unroll
        for (int k = 0; k < 4; k++) lo2r[k] = conv_lo(lv + 2 * k);

        float* __restrict__ hi2_out =
            out + OFF_HI2 + (size_t)row * (N0 / 4) + (size_t)chunk * (S / 4) + 4 * t;
        float4 h2 = make_float4(conv_hi(lv + 0), conv_hi(lv + 2),
                                conv_hi(lv + 4), conv_hi(lv + 6));
        *reinterpret_cast<float4*>(hi2_out) = h2;

        eh2[t + 1] = make_float4(lo2r[1], lo2r[2], lo2r[3], 0.0f);
        el2[t + 1] = make_float4(lo2r[0], lo2r[1], lo2r[2], 0.0f);
    }
    __syncthreads();

    // ---- Level 3: mv[i] = lo2[4t-3+i]; outputs j = 2t, 2t+1 ----
    {
        float4 hl = eh2[t];                   // lo2[4t-3..4t-1]
        float4 lr = el2[t + 2];               // lo2[4t+4..4t+6]
        float mv[10];
        mv[0] = hl.x; mv[1] = hl.y; mv[2] = hl.z;
        mv[3] = lo2r[0]; mv[4] = lo2r[1]; mv[5] = lo2r[2]; mv[6] = lo2r[3];
        mv[7] = lr.x; mv[8] = lr.y; mv[9] = lr.z;

        float* __restrict__ x0_out =
            out + (size_t)row * (N0 / 8) + (size_t)chunk * (S / 8) + 2 * t;
        float* __restrict__ hi3_out =
            out + OFF_HI3 + (size_t)row * (N0 / 8) + (size_t)chunk * (S / 8) + 2 * t;
        float2 lv2 = make_float2(conv_lo(mv + 0), conv_lo(mv + 2));
        float2 hv2 = make_float2(conv_hi(mv + 0), conv_hi(mv + 2));
        *reinterpret_cast<float2*>(x0_out)  = lv2;
        *reinterpret_cast<float2*>(hi3_out) = hv2;
    }
}

extern "C" void kernel_launch(void* const* d_in, const int* in_sizes, int n_in,
                              void* d_out, int out_size)
{
    const float* x = (const float*)d_in[0];
    float* out = (float*)d_out;
    dwt3_reg_kernel<<<NROWS * CHUNKS, THREADS>>>(x, out);
}